// round 1
// baseline (speedup 1.0000x reference)
#include <cuda_runtime.h>
#include <math.h>

#define NN 50000
#define EE 500000

// ---------------- scratch (static device allocations; no cudaMalloc) ----------------
__device__ float    g_nf[(size_t)NN * 256];        // node features (in_n <= 256)
__device__ float    g_node_out[(size_t)NN * 512];  // [f_ni(128) | f_nj(128) | h_src(256)]
__device__ float    g_efbuf[(size_t)EE * 128];     // edge features after layer 0
__device__ float    g_elog[(size_t)EE * 4];        // attention logits, then exp(e-m)
__device__ unsigned g_menc[(size_t)NN * 4];        // encoded segment max
__device__ float    g_s[(size_t)NN * 4];           // segment sum of exp
__device__ float    g_hnew[(size_t)NN * 256];      // aggregated messages
__device__ float    g_wcat[256 * 512];             // [W_ni | W_nj | W_src]
__device__ float    g_bcat[512];

// ---------------- helpers ----------------
__device__ __forceinline__ unsigned fenc(float f) {
    unsigned u = __float_as_uint(f);
    return (u & 0x80000000u) ? ~u : (u | 0x80000000u);
}
__device__ __forceinline__ float fdec(unsigned u) {
    return (u & 0x80000000u) ? __uint_as_float(u & 0x7FFFFFFFu) : __uint_as_float(~u);
}
__device__ __forceinline__ void red4(float* p, float4 v) {
    asm volatile("red.global.add.v4.f32 [%0], {%1,%2,%3,%4};"
                 :: "l"(p), "f"(v.x), "f"(v.y), "f"(v.z), "f"(v.w) : "memory");
}
__device__ __forceinline__ float elu_f(float v) { return v > 0.f ? v : expm1f(v); }
__device__ __forceinline__ float lrelu_f(float v) { return v > 0.f ? v : 0.01f * v; }

// ---------------- small kernels ----------------
__global__ void k_embed(const int* __restrict__ node_types,
                        const float* __restrict__ embed,
                        float* __restrict__ nf) {
    int i = blockIdx.x * 256 + threadIdx.x;
    if (i < NN * 128) {
        int n = i >> 7, c = i & 127;
        nf[(size_t)n * 128 + c] = embed[node_types[n] * 128 + c];
    }
}

__global__ void k_concat(const float* __restrict__ Wni, const float* __restrict__ Wnj,
                         const float* __restrict__ Wsrc, const float* __restrict__ bsrc,
                         float* __restrict__ Wcat, float* __restrict__ bcat, int in_n) {
    int i = blockIdx.x * 256 + threadIdx.x;
    if (i < in_n * 512) {
        int r = i >> 9, c = i & 511;
        float v;
        if (c < 128)      v = Wni[r * 128 + c];
        else if (c < 256) v = Wnj[r * 128 + (c - 128)];
        else              v = Wsrc[r * 256 + (c - 256)];
        Wcat[i] = v;
    }
    if (i < 512) bcat[i] = (i < 256) ? 0.f : bsrc[i - 256];
}

__global__ void k_clear(unsigned* __restrict__ m, float* __restrict__ s,
                        float* __restrict__ hnew) {
    int i = blockIdx.x * 256 + threadIdx.x;
    if (i < NN * 4) { m[i] = 0u; s[i] = 0.f; }
    if (i < NN * 256) hnew[i] = 0.f;
}

__global__ void k_elu(const float* __restrict__ in, float* __restrict__ out, int n) {
    int i = blockIdx.x * 256 + threadIdx.x;
    if (i < n) out[i] = elu_f(in[i]);
}

// ---------------- node GEMM: C(M,512) = A(M,K) @ B(K,512) + bias ----------------
__global__ __launch_bounds__(256) void gemm_node_kernel(
    const float* __restrict__ A, const float* __restrict__ B,
    const float* __restrict__ bias, float* __restrict__ C, int M, int K) {
    __shared__ float As[8][128];
    __shared__ float Bs[8][128];
    int tid = threadIdx.x;
    int tm = tid >> 4, tn = tid & 15;
    int row0 = blockIdx.x * 128;
    int col0 = blockIdx.y * 128;

    float acc[8][8];
#pragma unroll
    for (int i = 0; i < 8; i++)
#pragma unroll
        for (int j = 0; j < 8; j++) acc[i][j] = 0.f;

    int ar = tid >> 1, ac = (tid & 1) * 4;
    int br = tid >> 5, bc = (tid & 31) * 4;

    for (int k0 = 0; k0 < K; k0 += 8) {
        float4 av = make_float4(0.f, 0.f, 0.f, 0.f);
        int arow = row0 + ar;
        if (arow < M) av = *(const float4*)(A + (size_t)arow * K + k0 + ac);
        As[ac + 0][ar] = av.x; As[ac + 1][ar] = av.y;
        As[ac + 2][ar] = av.z; As[ac + 3][ar] = av.w;
        *(float4*)&Bs[br][bc] = *(const float4*)(B + (size_t)(k0 + br) * 512 + col0 + bc);
        __syncthreads();
#pragma unroll
        for (int kk = 0; kk < 8; kk++) {
            float4 a0 = *(const float4*)&As[kk][tm * 8];
            float4 a1 = *(const float4*)&As[kk][tm * 8 + 4];
            float4 b0 = *(const float4*)&Bs[kk][tn * 8];
            float4 b1 = *(const float4*)&Bs[kk][tn * 8 + 4];
            float a[8] = {a0.x, a0.y, a0.z, a0.w, a1.x, a1.y, a1.z, a1.w};
            float b[8] = {b0.x, b0.y, b0.z, b0.w, b1.x, b1.y, b1.z, b1.w};
#pragma unroll
            for (int i = 0; i < 8; i++)
#pragma unroll
                for (int j = 0; j < 8; j++) acc[i][j] += a[i] * b[j];
        }
        __syncthreads();
    }

    float bb[8];
#pragma unroll
    for (int j = 0; j < 8; j++) bb[j] = bias[col0 + tn * 8 + j];
#pragma unroll
    for (int i = 0; i < 8; i++) {
        int r = row0 + tm * 8 + i;
        if (r < M) {
            float* cp = C + (size_t)r * 512 + col0 + tn * 8;
            float4 v0 = make_float4(acc[i][0] + bb[0], acc[i][1] + bb[1],
                                    acc[i][2] + bb[2], acc[i][3] + bb[3]);
            float4 v1 = make_float4(acc[i][4] + bb[4], acc[i][5] + bb[5],
                                    acc[i][6] + bb[6], acc[i][7] + bb[7]);
            *(float4*)cp = v0;
            *(float4*)(cp + 4) = v1;
        }
    }
}

// ---------------- fused edge GEMM + assemble + leaky + logits + max + ELU ----------------
__global__ __launch_bounds__(256) void gemm_edge_kernel(
    const float* __restrict__ A, const float* __restrict__ W,
    const float* __restrict__ node_out,
    const int* __restrict__ src, const int* __restrict__ dst,
    const float* __restrict__ bias, const float* __restrict__ attn,
    float* __restrict__ ef_out, float* __restrict__ elog,
    unsigned* __restrict__ menc, int M, int K) {
    __shared__ float As[8][128];
    __shared__ float Bs[8][128];
    __shared__ float lsh[128][4];
    __shared__ int ssh[128], dsh[128];
    __shared__ float bsh[128], ash[128];

    int tid = threadIdx.x;
    int tm = tid >> 4, tn = tid & 15;
    int e0 = blockIdx.x * 128;

    if (tid < 128) {
        int e = e0 + tid;
        ssh[tid] = (e < M) ? src[e] : 0;
        dsh[tid] = (e < M) ? dst[e] : 0;
        bsh[tid] = bias[tid];
        ash[tid] = attn[tid];
    }
    { int zr = tid >> 2, zh = tid & 3; lsh[zr][zh] = 0.f; lsh[zr + 64][zh] = 0.f; }

    float acc[8][8];
#pragma unroll
    for (int i = 0; i < 8; i++)
#pragma unroll
        for (int j = 0; j < 8; j++) acc[i][j] = 0.f;

    int ar = tid >> 1, ac = (tid & 1) * 4;
    int br = tid >> 5, bc = (tid & 31) * 4;

    for (int k0 = 0; k0 < K; k0 += 8) {
        float4 av = make_float4(0.f, 0.f, 0.f, 0.f);
        int arow = e0 + ar;
        if (arow < M) av = *(const float4*)(A + (size_t)arow * K + k0 + ac);
        As[ac + 0][ar] = av.x; As[ac + 1][ar] = av.y;
        As[ac + 2][ar] = av.z; As[ac + 3][ar] = av.w;
        *(float4*)&Bs[br][bc] = *(const float4*)(W + (size_t)(k0 + br) * 128 + bc);
        __syncthreads();
#pragma unroll
        for (int kk = 0; kk < 8; kk++) {
            float4 a0 = *(const float4*)&As[kk][tm * 8];
            float4 a1 = *(const float4*)&As[kk][tm * 8 + 4];
            float4 b0 = *(const float4*)&Bs[kk][tn * 8];
            float4 b1 = *(const float4*)&Bs[kk][tn * 8 + 4];
            float a[8] = {a0.x, a0.y, a0.z, a0.w, a1.x, a1.y, a1.z, a1.w};
            float b[8] = {b0.x, b0.y, b0.z, b0.w, b1.x, b1.y, b1.z, b1.w};
#pragma unroll
            for (int i = 0; i < 8; i++)
#pragma unroll
                for (int j = 0; j < 8; j++) acc[i][j] += a[i] * b[j];
        }
        __syncthreads();
    }

    int head = tn >> 2;
#pragma unroll
    for (int i = 0; i < 8; i++) {
        int r = tm * 8 + i;
        int e = e0 + r;
        if (e < M) {
            int si = ssh[r], di = dsh[r];
            const float* fni = node_out + (size_t)si * 512 + tn * 8;
            const float* fnj = node_out + (size_t)di * 512 + 128 + tn * 8;
            float4 n0 = *(const float4*)fni;
            float4 n1 = *(const float4*)(fni + 4);
            float4 j0 = *(const float4*)fnj;
            float4 j1 = *(const float4*)(fnj + 4);
            float add[8] = {n0.x + j0.x, n0.y + j0.y, n0.z + j0.z, n0.w + j0.w,
                            n1.x + j1.x, n1.y + j1.y, n1.z + j1.z, n1.w + j1.w};
            float part = 0.f;
            float o[8];
#pragma unroll
            for (int j = 0; j < 8; j++) {
                float v = acc[i][j] + add[j] + bsh[tn * 8 + j];
                v = lrelu_f(v);
                part += v * ash[tn * 8 + j];
                o[j] = elu_f(v);
            }
            atomicAdd(&lsh[r][head], part);
            float* op = ef_out + (size_t)e * 128 + tn * 8;
            *(float4*)op = make_float4(o[0], o[1], o[2], o[3]);
            *(float4*)(op + 4) = make_float4(o[4], o[5], o[6], o[7]);
        }
    }
    __syncthreads();

    for (int t = tid; t < 512; t += 256) {
        int r = t >> 2, h = t & 3;
        int e = e0 + r;
        if (e < M) {
            float lg = lsh[r][h];
            elog[(size_t)e * 4 + h] = lg;
            atomicMax(&menc[(size_t)dsh[r] * 4 + h], fenc(lg));
        }
    }
}

// ---------------- segment softmax denom ----------------
__global__ void k_expsum(const int* __restrict__ dst, float* __restrict__ elog,
                         const unsigned* __restrict__ menc, float* __restrict__ s) {
    int e = blockIdx.x * 256 + threadIdx.x;
    if (e < EE) {
        int d = dst[e];
        float4 l = *(const float4*)(elog + (size_t)e * 4);
        float m0 = fdec(menc[(size_t)d * 4 + 0]);
        float m1 = fdec(menc[(size_t)d * 4 + 1]);
        float m2 = fdec(menc[(size_t)d * 4 + 2]);
        float m3 = fdec(menc[(size_t)d * 4 + 3]);
        float4 ee = make_float4(expf(l.x - m0), expf(l.y - m1),
                                expf(l.z - m2), expf(l.w - m3));
        red4(&s[(size_t)d * 4], ee);
        *(float4*)(elog + (size_t)e * 4) = ee;
    }
}

// ---------------- message aggregation: hnew[dst] += h_src[src] * alpha ----------------
__global__ __launch_bounds__(256) void k_msg(
    const int* __restrict__ src, const int* __restrict__ dst,
    const float* __restrict__ elog, const float* __restrict__ s,
    const float* __restrict__ node_out, float* __restrict__ hnew) {
    int e = blockIdx.x * 4 + (threadIdx.x >> 6);
    int q = threadIdx.x & 63;
    if (e < EE) {
        int si = src[e], di = dst[e];
        int h = q >> 4;
        float alpha = elog[(size_t)e * 4 + h] / s[(size_t)di * 4 + h];
        float4 v = *(const float4*)(node_out + (size_t)si * 512 + 256 + q * 4);
        red4(&hnew[(size_t)di * 256 + q * 4],
             make_float4(v.x * alpha, v.y * alpha, v.z * alpha, v.w * alpha));
    }
}

// ---------------- host ----------------
extern "C" void kernel_launch(void* const* d_in, const int* in_sizes, int n_in,
                              void* d_out, int out_size) {
    const int*   node_types = (const int*)d_in[0];
    const int*   src        = (const int*)d_in[1];
    const int*   dst        = (const int*)d_in[2];
    const float* efeats     = (const float*)d_in[3];
    const float* embed      = (const float*)d_in[4];
    const float* W_src[2] = {(const float*)d_in[5],  (const float*)d_in[12]};
    const float* b_src[2] = {(const float*)d_in[6],  (const float*)d_in[13]};
    const float* W_ni[2]  = {(const float*)d_in[7],  (const float*)d_in[14]};
    const float* W_nj[2]  = {(const float*)d_in[8],  (const float*)d_in[15]};
    const float* W_fij[2] = {(const float*)d_in[9],  (const float*)d_in[16]};
    const float* attn[2]  = {(const float*)d_in[10], (const float*)d_in[17]};
    const float* bias[2]  = {(const float*)d_in[11], (const float*)d_in[18]};

    float *nf, *node_out, *efbuf, *elog, *s, *hnew, *wcat, *bcat;
    unsigned* menc;
    cudaGetSymbolAddress((void**)&nf, g_nf);
    cudaGetSymbolAddress((void**)&node_out, g_node_out);
    cudaGetSymbolAddress((void**)&efbuf, g_efbuf);
    cudaGetSymbolAddress((void**)&elog, g_elog);
    cudaGetSymbolAddress((void**)&menc, g_menc);
    cudaGetSymbolAddress((void**)&s, g_s);
    cudaGetSymbolAddress((void**)&hnew, g_hnew);
    cudaGetSymbolAddress((void**)&wcat, g_wcat);
    cudaGetSymbolAddress((void**)&bcat, g_bcat);

    float* out_nf = (float*)d_out;              // (N, 256) ELU'd node features
    float* out_ef = out_nf + (size_t)NN * 256;  // (E, 128) ELU'd edge features

    k_embed<<<(NN * 128 + 255) / 256, 256>>>(node_types, embed, nf);

    const float* ef_in = efeats;
    for (int L = 0; L < 2; L++) {
        int in_n = L ? 256 : 128;
        int in_e = L ? 128 : 64;
        k_concat<<<(in_n * 512 + 255) / 256, 256>>>(W_ni[L], W_nj[L], W_src[L],
                                                    b_src[L], wcat, bcat, in_n);
        k_clear<<<(NN * 256 + 255) / 256, 256>>>(menc, s, hnew);
        dim3 gn((NN + 127) / 128, 4);
        gemm_node_kernel<<<gn, 256>>>(nf, wcat, bcat, node_out, NN, in_n);

        float* ef_out = L ? out_ef : efbuf;
        gemm_edge_kernel<<<(EE + 127) / 128, 256>>>(ef_in, W_fij[L], node_out,
                                                    src, dst, bias[L], attn[L],
                                                    ef_out, elog, menc, EE, in_e);
        k_expsum<<<(EE + 255) / 256, 256>>>(dst, elog, menc, s);
        k_msg<<<EE / 4, 256>>>(src, dst, elog, s, node_out, hnew);

        float* nf_out = L ? out_nf : nf;
        k_elu<<<(NN * 256 + 255) / 256, 256>>>(hnew, nf_out, NN * 256);
        ef_in = ef_out;
    }
}

// round 3
// speedup vs baseline: 1.0885x; 1.0885x over previous
#include <cuda_runtime.h>
#include <cuda_bf16.h>
#include <math.h>
#include <stdint.h>

#define NN 50000
#define EE 500000

// ---------------- scratch ----------------
__device__ float    g_nf[(size_t)NN * 256];
__device__ float    g_node_out[(size_t)NN * 512];  // [f_ni(128) | f_nj(128) | h_src(256)]
__device__ float    g_efbuf[(size_t)EE * 128];
__device__ float    g_elog[(size_t)EE * 4];
__device__ unsigned g_menc[(size_t)NN * 4];
__device__ float    g_s[(size_t)NN * 4];
__device__ float    g_hnew[(size_t)NN * 256];
__device__ float    g_bcat[512];
__device__ __nv_bfloat16 g_btn_hi[512 * 256];   // node weights, transposed [n][k]
__device__ __nv_bfloat16 g_btn_lo[512 * 256];
__device__ __nv_bfloat16 g_bte_hi[128 * 128];   // edge weights, transposed [n][k]
__device__ __nv_bfloat16 g_bte_lo[128 * 128];

// ---------------- helpers ----------------
__device__ __forceinline__ uint32_t smem_u32(const void* p) {
    uint32_t a;
    asm("{ .reg .u64 t; cvta.to.shared.u64 t, %1; cvt.u32.u64 %0, t; }" : "=r"(a) : "l"(p));
    return a;
}
__device__ __forceinline__ unsigned lds32(uint32_t a) {
    unsigned v;
    asm volatile("ld.shared.b32 %0, [%1];" : "=r"(v) : "r"(a));
    return v;
}
__device__ __forceinline__ void sts64(uint32_t a, unsigned x, unsigned y) {
    asm volatile("st.shared.v2.b32 [%0], {%1, %2};" :: "r"(a), "r"(x), "r"(y) : "memory");
}
__device__ __forceinline__ void sts128(uint32_t a, uint4 v) {
    asm volatile("st.shared.v4.b32 [%0], {%1, %2, %3, %4};"
                 :: "r"(a), "r"(v.x), "r"(v.y), "r"(v.z), "r"(v.w) : "memory");
}
__device__ __forceinline__ void mma_bf16(float& d0, float& d1, float& d2, float& d3,
                                         unsigned a0, unsigned a1, unsigned a2, unsigned a3,
                                         unsigned b0, unsigned b1) {
    asm volatile(
        "mma.sync.aligned.m16n8k16.row.col.f32.bf16.bf16.f32 "
        "{%0,%1,%2,%3}, {%4,%5,%6,%7}, {%8,%9}, {%0,%1,%2,%3};"
        : "+f"(d0), "+f"(d1), "+f"(d2), "+f"(d3)
        : "r"(a0), "r"(a1), "r"(a2), "r"(a3), "r"(b0), "r"(b1));
}
__device__ __forceinline__ void split2(float a, float b, unsigned& hi, unsigned& lo) {
    __nv_bfloat16 ah = __float2bfloat16_rn(a), bh = __float2bfloat16_rn(b);
    __nv_bfloat16 al = __float2bfloat16_rn(a - __bfloat162float(ah));
    __nv_bfloat16 bl = __float2bfloat16_rn(b - __bfloat162float(bh));
    hi = (unsigned)__bfloat16_as_ushort(ah) | ((unsigned)__bfloat16_as_ushort(bh) << 16);
    lo = (unsigned)__bfloat16_as_ushort(al) | ((unsigned)__bfloat16_as_ushort(bl) << 16);
}
__device__ __forceinline__ unsigned fenc(float f) {
    unsigned u = __float_as_uint(f);
    return (u & 0x80000000u) ? ~u : (u | 0x80000000u);
}
__device__ __forceinline__ float fdec(unsigned u) {
    return (u & 0x80000000u) ? __uint_as_float(u & 0x7FFFFFFFu) : __uint_as_float(~u);
}
__device__ __forceinline__ void red4(float* p, float4 v) {
    asm volatile("red.global.add.v4.f32 [%0], {%1,%2,%3,%4};"
                 :: "l"(p), "f"(v.x), "f"(v.y), "f"(v.z), "f"(v.w) : "memory");
}
__device__ __forceinline__ float elu_f(float v)   { return v > 0.f ? v : expm1f(v); }
__device__ __forceinline__ float lrelu_f(float v) { return v > 0.f ? v : 0.01f * v; }

// ---------------- smem layout (bytes) ----------------
// Tiles: A_hi | A_lo | B_hi | B_lo, each 128 rows x 80B (KC=32 bf16, pad 40)
#define AHI   0
#define ALO   10240
#define BHI   20480
#define BLO   30720
#define TILES_END 40960
// node kernel: bias after tiles
#define NODE_BIAS 40960
#define NODE_SMEM (40960 + 2048)
// edge kernel: stage + misc after tiles
#define EST      40960             // 128 x 132 fp32 = 67584
#define ESRC     108544
#define EDST     109056
#define EBIAS    109568
#define EATTN    110080
#define ELSH     110592            // 128*4 fp32 = 2048
#define EDGE_SMEM 112640

// ---------------- small kernels ----------------
__global__ void k_embed(const int* __restrict__ node_types,
                        const float* __restrict__ embed, float* __restrict__ nf) {
    int i = blockIdx.x * 256 + threadIdx.x;
    if (i < NN * 128) {
        int n = i >> 7, c = i & 127;
        nf[(size_t)n * 128 + c] = embed[node_types[n] * 128 + c];
    }
}

__global__ void k_prep(const float* __restrict__ Wni, const float* __restrict__ Wnj,
                       const float* __restrict__ Wsrc, const float* __restrict__ bsrc,
                       const float* __restrict__ Wfij,
                       float* __restrict__ bcat,
                       __nv_bfloat16* __restrict__ btn_hi, __nv_bfloat16* __restrict__ btn_lo,
                       __nv_bfloat16* __restrict__ bte_hi, __nv_bfloat16* __restrict__ bte_lo,
                       int in_n, int in_e) {
    int i = blockIdx.x * 256 + threadIdx.x;
    int nn = 512 * in_n;
    if (i < nn) {
        int n = i / in_n, k = i - n * in_n;
        float v;
        if (n < 128)      v = Wni[k * 128 + n];
        else if (n < 256) v = Wnj[k * 128 + (n - 128)];
        else              v = Wsrc[k * 256 + (n - 256)];
        __nv_bfloat16 h = __float2bfloat16_rn(v);
        __nv_bfloat16 l = __float2bfloat16_rn(v - __bfloat162float(h));
        btn_hi[(size_t)n * in_n + k] = h;
        btn_lo[(size_t)n * in_n + k] = l;
    } else if (i < nn + 128 * in_e) {
        int j = i - nn;
        int n = j / in_e, k = j - n * in_e;
        float v = Wfij[k * 128 + n];
        __nv_bfloat16 h = __float2bfloat16_rn(v);
        __nv_bfloat16 l = __float2bfloat16_rn(v - __bfloat162float(h));
        bte_hi[(size_t)n * in_e + k] = h;
        bte_lo[(size_t)n * in_e + k] = l;
    }
    if (i < 512) bcat[i] = (i < 256) ? 0.f : bsrc[i - 256];
}

__global__ void k_clear(unsigned* __restrict__ m, float* __restrict__ s,
                        float* __restrict__ hnew) {
    int i = blockIdx.x * 256 + threadIdx.x;
    if (i < NN * 4) { m[i] = 0u; s[i] = 0.f; }
    if (i < NN * 256) hnew[i] = 0.f;
}

__global__ void k_elu(const float* __restrict__ in, float* __restrict__ out, int n) {
    int i = blockIdx.x * 256 + threadIdx.x;
    if (i < n) out[i] = elu_f(in[i]);
}

// ---------------- mma mainloop (bf16 split, 128x128 tile, 8 warps 4x2) ----------------
__device__ __forceinline__ void mma_mainloop(
    uint32_t sb, const float* __restrict__ A,
    const __nv_bfloat16* __restrict__ Bth, const __nv_bfloat16* __restrict__ Btl,
    int row0, int n0, int M, int K, float acc[2][8][4]) {
    int tid = threadIdx.x;
    int lane = tid & 31, wid = tid >> 5;
    int g = lane >> 2, tig = lane & 3;
    int wm = wid & 3, wn = wid >> 2;

    for (int k0 = 0; k0 < K; k0 += 32) {
        // ---- A tile: fp32 -> hi/lo bf16, [128 x 32], row stride 80B ----
        {
            int r = tid >> 1, hk = tid & 1;
            int arow = row0 + r;
            const float* ap = A + (size_t)arow * K + k0 + hk * 16;
            uint32_t ah = sb + AHI + r * 80 + hk * 32;
            uint32_t al = sb + ALO + r * 80 + hk * 32;
#pragma unroll
            for (int q = 0; q < 4; q++) {
                float4 v = make_float4(0.f, 0.f, 0.f, 0.f);
                if (arow < M) v = *(const float4*)(ap + q * 4);
                unsigned h0, l0, h1, l1;
                split2(v.x, v.y, h0, l0);
                split2(v.z, v.w, h1, l1);
                sts64(ah + q * 8, h0, h1);
                sts64(al + q * 8, l0, l1);
            }
        }
        // ---- B tile: bf16 hi/lo [128 x 32] ----
        {
#pragma unroll
            for (int i = 0; i < 2; i++) {
                int c = tid + i * 256;
                int n = c >> 2, k8 = c & 3;
                size_t go = (size_t)(n0 + n) * K + k0 + k8 * 8;
                uint4 hv = *(const uint4*)(Bth + go);
                uint4 lv = *(const uint4*)(Btl + go);
                uint32_t ba = sb + BHI + n * 80 + k8 * 16;
                sts128(ba, hv);
                sts128(ba + (BLO - BHI), lv);
            }
        }
        __syncthreads();
#pragma unroll
        for (int ks = 0; ks < 2; ks++) {
            unsigned ahr[2][4], alr[2][4];
            uint32_t abase = sb + (wm * 32 + g) * 80 + ks * 32 + tig * 4;
#pragma unroll
            for (int mt = 0; mt < 2; mt++) {
                uint32_t a0 = abase + mt * (16 * 80);
                ahr[mt][0] = lds32(a0);
                ahr[mt][1] = lds32(a0 + 8 * 80);
                ahr[mt][2] = lds32(a0 + 16);
                ahr[mt][3] = lds32(a0 + 8 * 80 + 16);
                uint32_t a0l = a0 + ALO;
                alr[mt][0] = lds32(a0l);
                alr[mt][1] = lds32(a0l + 8 * 80);
                alr[mt][2] = lds32(a0l + 16);
                alr[mt][3] = lds32(a0l + 8 * 80 + 16);
            }
            uint32_t bbase = sb + BHI + (wn * 64 + g) * 80 + ks * 32 + tig * 4;
#pragma unroll
            for (int nt = 0; nt < 8; nt++) {
                uint32_t b0a = bbase + nt * (8 * 80);
                unsigned bh0 = lds32(b0a), bh1 = lds32(b0a + 16);
                unsigned bl0 = lds32(b0a + (BLO - BHI)), bl1 = lds32(b0a + (BLO - BHI) + 16);
#pragma unroll
                for (int mt = 0; mt < 2; mt++) {
                    float* d = acc[mt][nt];
                    mma_bf16(d[0], d[1], d[2], d[3],
                             ahr[mt][0], ahr[mt][1], ahr[mt][2], ahr[mt][3], bh0, bh1);
                    mma_bf16(d[0], d[1], d[2], d[3],
                             ahr[mt][0], ahr[mt][1], ahr[mt][2], ahr[mt][3], bl0, bl1);
                    mma_bf16(d[0], d[1], d[2], d[3],
                             alr[mt][0], alr[mt][1], alr[mt][2], alr[mt][3], bh0, bh1);
                }
            }
        }
        __syncthreads();
    }
}

// ---------------- node GEMM: node_out(M,512) = A(M,K) @ Bt^T + bias ----------------
__global__ __launch_bounds__(256) void gemm_node_mma(
    const float* __restrict__ A,
    const __nv_bfloat16* __restrict__ Bth, const __nv_bfloat16* __restrict__ Btl,
    const float* __restrict__ bias, float* __restrict__ Cout, int M, int K) {
    extern __shared__ __align__(16) char smem[];
    uint32_t sb = smem_u32(smem);
    float* bsm = (float*)(smem + NODE_BIAS);
    int tid = threadIdx.x;
    ((float2*)bsm)[tid] = ((const float2*)bias)[tid];  // 512 floats

    int row0 = blockIdx.x * 128, n0 = blockIdx.y * 128;
    float acc[2][8][4];
#pragma unroll
    for (int mt = 0; mt < 2; mt++)
#pragma unroll
        for (int nt = 0; nt < 8; nt++)
#pragma unroll
            for (int q = 0; q < 4; q++) acc[mt][nt][q] = 0.f;

    mma_mainloop(sb, A, Bth, Btl, row0, n0, M, K, acc);

    int lane = tid & 31, wid = tid >> 5;
    int g = lane >> 2, tig = lane & 3;
    int wm = wid & 3, wn = wid >> 2;
#pragma unroll
    for (int mt = 0; mt < 2; mt++) {
        int r0 = row0 + wm * 32 + mt * 16 + g;
#pragma unroll
        for (int nt = 0; nt < 8; nt++) {
            int cc = n0 + wn * 64 + nt * 8 + 2 * tig;
            float b0 = bsm[cc], b1 = bsm[cc + 1];
            float* d = acc[mt][nt];
            if (r0 < M)
                *(float2*)(Cout + (size_t)r0 * 512 + cc) = make_float2(d[0] + b0, d[1] + b1);
            if (r0 + 8 < M)
                *(float2*)(Cout + (size_t)(r0 + 8) * 512 + cc) = make_float2(d[2] + b0, d[3] + b1);
        }
    }
}

// ---------------- edge GEMM fused epilogue ----------------
__global__ __launch_bounds__(256) void gemm_edge_mma(
    const float* __restrict__ A,
    const __nv_bfloat16* __restrict__ Bth, const __nv_bfloat16* __restrict__ Btl,
    const float* __restrict__ node_out,
    const int* __restrict__ src, const int* __restrict__ dst,
    const float* __restrict__ bias, const float* __restrict__ attn,
    float* __restrict__ ef_out, float* __restrict__ elog,
    unsigned* __restrict__ menc, int M, int K) {
    extern __shared__ __align__(16) char smem[];
    uint32_t sb = smem_u32(smem);
    float* stage = (float*)(smem + EST);     // [128][132]
    int*   ssh = (int*)(smem + ESRC);
    int*   dsh = (int*)(smem + EDST);
    float* bsh = (float*)(smem + EBIAS);
    float* ash = (float*)(smem + EATTN);
    float* lsh = (float*)(smem + ELSH);

    int tid = threadIdx.x;
    int e0 = blockIdx.x * 128;
    if (tid < 128) {
        int e = e0 + tid;
        ssh[tid] = (e < M) ? src[e] : 0;
        dsh[tid] = (e < M) ? dst[e] : 0;
        bsh[tid] = bias[tid];
        ash[tid] = attn[tid];
    }

    float acc[2][8][4];
#pragma unroll
    for (int mt = 0; mt < 2; mt++)
#pragma unroll
        for (int nt = 0; nt < 8; nt++)
#pragma unroll
            for (int q = 0; q < 4; q++) acc[mt][nt][q] = 0.f;

    mma_mainloop(sb, A, Bth, Btl, e0, 0, M, K, acc);

    int lane = tid & 31, wid = tid >> 5;
    int g = lane >> 2, tig = lane & 3;
    int wm = wid & 3, wn = wid >> 2;
#pragma unroll
    for (int mt = 0; mt < 2; mt++) {
        int r = wm * 32 + mt * 16 + g;
#pragma unroll
        for (int nt = 0; nt < 8; nt++) {
            int cc = wn * 64 + nt * 8 + 2 * tig;
            float* d = acc[mt][nt];
            *(float2*)&stage[r * 132 + cc] = make_float2(d[0], d[1]);
            *(float2*)&stage[(r + 8) * 132 + cc] = make_float2(d[2], d[3]);
        }
    }
    __syncthreads();

    {
        int r = tid & 127, hc = tid >> 7;   // hc: which 64-col half
        int e = e0 + r;
        if (e < M) {
            int si = ssh[r], dj = dsh[r];
            const float* pni = node_out + (size_t)si * 512 + hc * 64;
            const float* pnj = node_out + (size_t)dj * 512 + 128 + hc * 64;
            const float* sp = stage + r * 132 + hc * 64;
            float* op = ef_out + (size_t)e * 128 + hc * 64;
            float part[2] = {0.f, 0.f};
#pragma unroll
            for (int q = 0; q < 16; q++) {
                int c = hc * 64 + q * 4;
                float4 sv = *(const float4*)(sp + q * 4);
                float4 a = *(const float4*)(pni + q * 4);
                float4 b = *(const float4*)(pnj + q * 4);
                float4 o;
                float v;
                v = sv.x + a.x + b.x + bsh[c + 0];
                v = lrelu_f(v); part[q >> 3] += v * ash[c + 0]; o.x = elu_f(v);
                v = sv.y + a.y + b.y + bsh[c + 1];
                v = lrelu_f(v); part[q >> 3] += v * ash[c + 1]; o.y = elu_f(v);
                v = sv.z + a.z + b.z + bsh[c + 2];
                v = lrelu_f(v); part[q >> 3] += v * ash[c + 2]; o.z = elu_f(v);
                v = sv.w + a.w + b.w + bsh[c + 3];
                v = lrelu_f(v); part[q >> 3] += v * ash[c + 3]; o.w = elu_f(v);
                *(float4*)(op + q * 4) = o;
            }
            lsh[r * 4 + hc * 2 + 0] = part[0];
            lsh[r * 4 + hc * 2 + 1] = part[1];
        }
    }
    __syncthreads();

    for (int t = tid; t < 512; t += 256) {
        int r2 = t >> 2, h = t & 3;
        int e2 = e0 + r2;
        if (e2 < M) {
            float lg = lsh[r2 * 4 + h];
            elog[(size_t)e2 * 4 + h] = lg;
            atomicMax(&menc[(size_t)dsh[r2] * 4 + h], fenc(lg));
        }
    }
}

// ---------------- segment softmax denom ----------------
__global__ void k_expsum(const int* __restrict__ dst, float* __restrict__ elog,
                         const unsigned* __restrict__ menc, float* __restrict__ s) {
    int e = blockIdx.x * 256 + threadIdx.x;
    if (e < EE) {
        int d = dst[e];
        float4 l = *(const float4*)(elog + (size_t)e * 4);
        float m0 = fdec(menc[(size_t)d * 4 + 0]);
        float m1 = fdec(menc[(size_t)d * 4 + 1]);
        float m2 = fdec(menc[(size_t)d * 4 + 2]);
        float m3 = fdec(menc[(size_t)d * 4 + 3]);
        float4 ee = make_float4(expf(l.x - m0), expf(l.y - m1),
                                expf(l.z - m2), expf(l.w - m3));
        red4(&s[(size_t)d * 4], ee);
        *(float4*)(elog + (size_t)e * 4) = ee;
    }
}

// ---------------- message aggregation ----------------
__global__ __launch_bounds__(256) void k_msg(
    const int* __restrict__ src, const int* __restrict__ dst,
    const float* __restrict__ elog, const float* __restrict__ s,
    const float* __restrict__ node_out, float* __restrict__ hnew) {
    int e = blockIdx.x * 4 + (threadIdx.x >> 6);
    int q = threadIdx.x & 63;
    if (e < EE) {
        int si = src[e], di = dst[e];
        int h = q >> 4;
        float alpha = elog[(size_t)e * 4 + h] / s[(size_t)di * 4 + h];
        float4 v = *(const float4*)(node_out + (size_t)si * 512 + 256 + q * 4);
        red4(&hnew[(size_t)di * 256 + q * 4],
             make_float4(v.x * alpha, v.y * alpha, v.z * alpha, v.w * alpha));
    }
}

// ---------------- host ----------------
extern "C" void kernel_launch(void* const* d_in, const int* in_sizes, int n_in,
                              void* d_out, int out_size) {
    const int*   node_types = (const int*)d_in[0];
    const int*   src        = (const int*)d_in[1];
    const int*   dst        = (const int*)d_in[2];
    const float* efeats     = (const float*)d_in[3];
    const float* embed      = (const float*)d_in[4];
    const float* W_src[2] = {(const float*)d_in[5],  (const float*)d_in[12]};
    const float* b_src[2] = {(const float*)d_in[6],  (const float*)d_in[13]};
    const float* W_ni[2]  = {(const float*)d_in[7],  (const float*)d_in[14]};
    const float* W_nj[2]  = {(const float*)d_in[8],  (const float*)d_in[15]};
    const float* W_fij[2] = {(const float*)d_in[9],  (const float*)d_in[16]};
    const float* attn[2]  = {(const float*)d_in[10], (const float*)d_in[17]};
    const float* bias[2]  = {(const float*)d_in[11], (const float*)d_in[18]};

    float *nf, *node_out, *efbuf, *elog, *s, *hnew, *bcat;
    unsigned* menc;
    __nv_bfloat16 *btnh, *btnl, *bteh, *btel;
    cudaGetSymbolAddress((void**)&nf, g_nf);
    cudaGetSymbolAddress((void**)&node_out, g_node_out);
    cudaGetSymbolAddress((void**)&efbuf, g_efbuf);
    cudaGetSymbolAddress((void**)&elog, g_elog);
    cudaGetSymbolAddress((void**)&menc, g_menc);
    cudaGetSymbolAddress((void**)&s, g_s);
    cudaGetSymbolAddress((void**)&hnew, g_hnew);
    cudaGetSymbolAddress((void**)&bcat, g_bcat);
    cudaGetSymbolAddress((void**)&btnh, g_btn_hi);
    cudaGetSymbolAddress((void**)&btnl, g_btn_lo);
    cudaGetSymbolAddress((void**)&bteh, g_bte_hi);
    cudaGetSymbolAddress((void**)&btel, g_bte_lo);

    cudaFuncSetAttribute(gemm_node_mma, cudaFuncAttributeMaxDynamicSharedMemorySize, NODE_SMEM);
    cudaFuncSetAttribute(gemm_edge_mma, cudaFuncAttributeMaxDynamicSharedMemorySize, EDGE_SMEM);

    float* out_nf = (float*)d_out;
    float* out_ef = out_nf + (size_t)NN * 256;

    k_embed<<<(NN * 128 + 255) / 256, 256>>>(node_types, embed, nf);

    const float* ef_in = efeats;
    for (int L = 0; L < 2; L++) {
        int in_n = L ? 256 : 128;
        int in_e = L ? 128 : 64;
        int prep_items = 512 * in_n + 128 * in_e;
        k_prep<<<(prep_items + 255) / 256, 256>>>(W_ni[L], W_nj[L], W_src[L], b_src[L],
                                                  W_fij[L], bcat, btnh, btnl, bteh, btel,
                                                  in_n, in_e);
        k_clear<<<(NN * 256 + 255) / 256, 256>>>(menc, s, hnew);

        dim3 gn((NN + 127) / 128, 4);
        gemm_node_mma<<<gn, 256, NODE_SMEM>>>(nf, btnh, btnl, bcat, node_out, NN, in_n);

        float* ef_out = L ? out_ef : efbuf;
        gemm_edge_mma<<<(EE + 127) / 128, 256, EDGE_SMEM>>>(ef_in, bteh, btel, node_out,
                                                            src, dst, bias[L], attn[L],
                                                            ef_out, elog, menc, EE, in_e);
        k_expsum<<<(EE + 255) / 256, 256>>>(dst, elog, menc, s);
        k_msg<<<EE / 4, 256>>>(src, dst, elog, s, node_out, hnew);

        float* nf_out = L ? out_nf : nf;
        k_elu<<<(NN * 256 + 255) / 256, 256>>>(hnew, nf_out, NN * 256);
        ef_in = ef_out;
    }
}

// round 4
// speedup vs baseline: 1.3164x; 1.2094x over previous
#include <cuda_runtime.h>
#include <cuda_bf16.h>
#include <math.h>
#include <stdint.h>

#define NN 50000
#define EE 500000

// ---------------- scratch ----------------
__device__ float    g_nf[(size_t)NN * 256];
__device__ float    g_node_out[(size_t)NN * 512];  // [f_ni(128) | f_nj(128) | h_src(256)]
__device__ float    g_efbuf[(size_t)EE * 128];
__device__ float    g_elog[(size_t)EE * 4];
__device__ unsigned g_menc[(size_t)NN * 4];
__device__ float    g_s[(size_t)NN * 4];
__device__ float    g_hnew[(size_t)NN * 256];
__device__ float    g_bcat[512];
__device__ __nv_bfloat16 g_btn_hi[512 * 256];
__device__ __nv_bfloat16 g_btn_lo[512 * 256];
__device__ __nv_bfloat16 g_bte_hi[128 * 128];
__device__ __nv_bfloat16 g_bte_lo[128 * 128];

// ---------------- helpers ----------------
__device__ __forceinline__ uint32_t smem_u32(const void* p) {
    uint32_t a;
    asm("{ .reg .u64 t; cvta.to.shared.u64 t, %1; cvt.u32.u64 %0, t; }" : "=r"(a) : "l"(p));
    return a;
}
__device__ __forceinline__ unsigned lds32(uint32_t a) {
    unsigned v;
    asm volatile("ld.shared.b32 %0, [%1];" : "=r"(v) : "r"(a));
    return v;
}
__device__ __forceinline__ void sts128(uint32_t a, uint4 v) {
    asm volatile("st.shared.v4.b32 [%0], {%1, %2, %3, %4};"
                 :: "r"(a), "r"(v.x), "r"(v.y), "r"(v.z), "r"(v.w) : "memory");
}
#define CP_ASYNC16(dst, src) \
    asm volatile("cp.async.ca.shared.global [%0], [%1], 16;" :: "r"(dst), "l"(src) : "memory")
#define CP_COMMIT() asm volatile("cp.async.commit_group;" ::: "memory")
#define CP_WAIT0()  asm volatile("cp.async.wait_group 0;" ::: "memory")

__device__ __forceinline__ void mma_bf16(float& d0, float& d1, float& d2, float& d3,
                                         unsigned a0, unsigned a1, unsigned a2, unsigned a3,
                                         unsigned b0, unsigned b1) {
    asm volatile(
        "mma.sync.aligned.m16n8k16.row.col.f32.bf16.bf16.f32 "
        "{%0,%1,%2,%3}, {%4,%5,%6,%7}, {%8,%9}, {%0,%1,%2,%3};"
        : "+f"(d0), "+f"(d1), "+f"(d2), "+f"(d3)
        : "r"(a0), "r"(a1), "r"(a2), "r"(a3), "r"(b0), "r"(b1));
}
__device__ __forceinline__ void split2(float a, float b, unsigned& hi, unsigned& lo) {
    __nv_bfloat16 ah = __float2bfloat16_rn(a), bh = __float2bfloat16_rn(b);
    __nv_bfloat16 al = __float2bfloat16_rn(a - __bfloat162float(ah));
    __nv_bfloat16 bl = __float2bfloat16_rn(b - __bfloat162float(bh));
    hi = (unsigned)__bfloat16_as_ushort(ah) | ((unsigned)__bfloat16_as_ushort(bh) << 16);
    lo = (unsigned)__bfloat16_as_ushort(al) | ((unsigned)__bfloat16_as_ushort(bl) << 16);
}
__device__ __forceinline__ unsigned fenc(float f) {
    unsigned u = __float_as_uint(f);
    return (u & 0x80000000u) ? ~u : (u | 0x80000000u);
}
__device__ __forceinline__ float fdec(unsigned u) {
    return (u & 0x80000000u) ? __uint_as_float(u & 0x7FFFFFFFu) : __uint_as_float(~u);
}
__device__ __forceinline__ void red4(float* p, float4 v) {
    asm volatile("red.global.add.v4.f32 [%0], {%1,%2,%3,%4};"
                 :: "l"(p), "f"(v.x), "f"(v.y), "f"(v.z), "f"(v.w) : "memory");
}
__device__ __forceinline__ float elu_f(float v)   { return v > 0.f ? v : expm1f(v); }
__device__ __forceinline__ float lrelu_f(float v) { return v > 0.f ? v : 0.01f * v; }

// ---------------- smem layout (bytes) ----------------
// Two tile buffers, each: A_hi | A_lo | B_hi | B_lo (128 rows x 80B, KC=32)
#define AHI    0
#define ALO    10240
#define BHI    20480
#define BLO    30720
#define BUFSZ  40960
#define TILES_END 81920
// node kernel
#define NODE_BIAS 81920
#define NODE_SMEM (81920 + 2048)
// edge kernel: stage overlaps the tile buffers (used only after mainloop)
#define EST      0                 // 128 x 132 fp32 = 67584 (< 81920)
#define ESRC     81920
#define EDST     82432
#define EBIAS    82944
#define EATTN    83456
#define ELSH     83968             // 128*4 fp32 = 2048
#define EDGE_SMEM 86016

// ---------------- small kernels ----------------
__global__ void k_embed(const int* __restrict__ node_types,
                        const float* __restrict__ embed, float* __restrict__ nf) {
    int i = blockIdx.x * 256 + threadIdx.x;
    if (i < NN * 128) {
        int n = i >> 7, c = i & 127;
        nf[(size_t)n * 128 + c] = embed[node_types[n] * 128 + c];
    }
}

__global__ void k_prep(const float* __restrict__ Wni, const float* __restrict__ Wnj,
                       const float* __restrict__ Wsrc, const float* __restrict__ bsrc,
                       const float* __restrict__ Wfij,
                       float* __restrict__ bcat,
                       __nv_bfloat16* __restrict__ btn_hi, __nv_bfloat16* __restrict__ btn_lo,
                       __nv_bfloat16* __restrict__ bte_hi, __nv_bfloat16* __restrict__ bte_lo,
                       int in_n, int in_e) {
    int i = blockIdx.x * 256 + threadIdx.x;
    int nn = 512 * in_n;
    if (i < nn) {
        int n = i / in_n, k = i - n * in_n;
        float v;
        if (n < 128)      v = Wni[k * 128 + n];
        else if (n < 256) v = Wnj[k * 128 + (n - 128)];
        else              v = Wsrc[k * 256 + (n - 256)];
        __nv_bfloat16 h = __float2bfloat16_rn(v);
        __nv_bfloat16 l = __float2bfloat16_rn(v - __bfloat162float(h));
        btn_hi[(size_t)n * in_n + k] = h;
        btn_lo[(size_t)n * in_n + k] = l;
    } else if (i < nn + 128 * in_e) {
        int j = i - nn;
        int n = j / in_e, k = j - n * in_e;
        float v = Wfij[k * 128 + n];
        __nv_bfloat16 h = __float2bfloat16_rn(v);
        __nv_bfloat16 l = __float2bfloat16_rn(v - __bfloat162float(h));
        bte_hi[(size_t)n * in_e + k] = h;
        bte_lo[(size_t)n * in_e + k] = l;
    }
    if (i < 512) bcat[i] = (i < 256) ? 0.f : bsrc[i - 256];
}

__global__ void k_clear(unsigned* __restrict__ m, float* __restrict__ s,
                        float* __restrict__ hnew) {
    int i = blockIdx.x * 256 + threadIdx.x;
    if (i < NN * 4) { m[i] = 0u; s[i] = 0.f; }
    if (i < NN * 256) hnew[i] = 0.f;
}

__global__ void k_elu(const float* __restrict__ in, float* __restrict__ out, int n) {
    int i = blockIdx.x * 256 + threadIdx.x;
    if (i < n) out[i] = elu_f(in[i]);
}

// ---------------- pipelined mainloop pieces ----------------
__device__ __forceinline__ void b_cpasync(uint32_t sb, int buf,
                                          const __nv_bfloat16* __restrict__ Bth,
                                          const __nv_bfloat16* __restrict__ Btl,
                                          int n0, int K, int k0) {
    int tid = threadIdx.x;
#pragma unroll
    for (int i = 0; i < 2; i++) {
        int c = tid + i * 256;
        int n = c >> 2, k16 = c & 3;
        size_t go = (size_t)(n0 + n) * K + k0 + k16 * 8;
        uint32_t da = sb + buf * BUFSZ + BHI + n * 80 + k16 * 16;
        CP_ASYNC16(da, Bth + go);
        CP_ASYNC16(da + (BLO - BHI), Btl + go);
    }
}

__device__ __forceinline__ void a_convert_sts(uint32_t sb, int buf, int r, int hk,
                                              const float4 pa[4]) {
    uint32_t ah = sb + buf * BUFSZ + AHI + r * 80 + hk * 32;
    uint32_t al = ah + (ALO - AHI);
#pragma unroll
    for (int q = 0; q < 2; q++) {
        unsigned h0, l0, h1, l1, h2, l2, h3, l3;
        split2(pa[2 * q].x,     pa[2 * q].y,     h0, l0);
        split2(pa[2 * q].z,     pa[2 * q].w,     h1, l1);
        split2(pa[2 * q + 1].x, pa[2 * q + 1].y, h2, l2);
        split2(pa[2 * q + 1].z, pa[2 * q + 1].w, h3, l3);
        sts128(ah + q * 16, make_uint4(h0, h1, h2, h3));
        sts128(al + q * 16, make_uint4(l0, l1, l2, l3));
    }
}

__device__ __forceinline__ void mma_compute(uint32_t sb, int buf, float acc[2][8][4]) {
    int tid = threadIdx.x, lane = tid & 31, wid = tid >> 5;
    int g = lane >> 2, tig = lane & 3;
    int wm = wid & 3, wn = wid >> 2;
    uint32_t bo = sb + buf * BUFSZ;
#pragma unroll
    for (int ks = 0; ks < 2; ks++) {
        unsigned ahr[2][4], alr[2][4];
        uint32_t abase = bo + AHI + (wm * 32 + g) * 80 + ks * 32 + tig * 4;
#pragma unroll
        for (int mt = 0; mt < 2; mt++) {
            uint32_t a0 = abase + mt * (16 * 80);
            ahr[mt][0] = lds32(a0);
            ahr[mt][1] = lds32(a0 + 8 * 80);
            ahr[mt][2] = lds32(a0 + 16);
            ahr[mt][3] = lds32(a0 + 8 * 80 + 16);
            uint32_t a0l = a0 + (ALO - AHI);
            alr[mt][0] = lds32(a0l);
            alr[mt][1] = lds32(a0l + 8 * 80);
            alr[mt][2] = lds32(a0l + 16);
            alr[mt][3] = lds32(a0l + 8 * 80 + 16);
        }
        uint32_t bbase = bo + BHI + (wn * 64 + g) * 80 + ks * 32 + tig * 4;
#pragma unroll
        for (int nt = 0; nt < 8; nt++) {
            uint32_t b0a = bbase + nt * (8 * 80);
            unsigned bh0 = lds32(b0a), bh1 = lds32(b0a + 16);
            unsigned bl0 = lds32(b0a + (BLO - BHI)), bl1 = lds32(b0a + (BLO - BHI) + 16);
#pragma unroll
            for (int mt = 0; mt < 2; mt++) {
                float* d = acc[mt][nt];
                mma_bf16(d[0], d[1], d[2], d[3],
                         ahr[mt][0], ahr[mt][1], ahr[mt][2], ahr[mt][3], bh0, bh1);
                mma_bf16(d[0], d[1], d[2], d[3],
                         ahr[mt][0], ahr[mt][1], ahr[mt][2], ahr[mt][3], bl0, bl1);
                mma_bf16(d[0], d[1], d[2], d[3],
                         alr[mt][0], alr[mt][1], alr[mt][2], alr[mt][3], bh0, bh1);
            }
        }
    }
}

__device__ __forceinline__ void mma_mainloop(
    uint32_t sb, const float* __restrict__ A,
    const __nv_bfloat16* __restrict__ Bth, const __nv_bfloat16* __restrict__ Btl,
    int row0, int n0, int M, int K, float acc[2][8][4]) {
    int tid = threadIdx.x;
    int r = tid >> 1, hk = tid & 1;
    int arow = row0 + r;
    bool aval = arow < M;
    const float* abase = A + (size_t)arow * K + hk * 16;
    int nst = K >> 5;

    float4 pa[4];
    const float4 z4 = make_float4(0.f, 0.f, 0.f, 0.f);
#pragma unroll
    for (int q = 0; q < 4; q++) pa[q] = aval ? *(const float4*)(abase + q * 4) : z4;
    b_cpasync(sb, 0, Bth, Btl, n0, K, 0);
    CP_COMMIT();
    a_convert_sts(sb, 0, r, hk, pa);
    CP_WAIT0();
    __syncthreads();

    for (int s = 0; s < nst; s++) {
        int buf = s & 1, nb = buf ^ 1;
        bool more = (s + 1) < nst;
        if (more) {
            b_cpasync(sb, nb, Bth, Btl, n0, K, (s + 1) * 32);
            CP_COMMIT();
            const float* ap = abase + (s + 1) * 32;
#pragma unroll
            for (int q = 0; q < 4; q++) pa[q] = aval ? *(const float4*)(ap + q * 4) : z4;
        }
        mma_compute(sb, buf, acc);
        if (more) {
            a_convert_sts(sb, nb, r, hk, pa);
            CP_WAIT0();
        }
        __syncthreads();
    }
}

// ---------------- node GEMM ----------------
__global__ __launch_bounds__(256, 2) void gemm_node_mma(
    const float* __restrict__ A,
    const __nv_bfloat16* __restrict__ Bth, const __nv_bfloat16* __restrict__ Btl,
    const float* __restrict__ bias, float* __restrict__ Cout, int M, int K) {
    extern __shared__ __align__(16) char smem[];
    uint32_t sb = smem_u32(smem);
    float* bsm = (float*)(smem + NODE_BIAS);
    int tid = threadIdx.x;
    ((float2*)bsm)[tid] = ((const float2*)bias)[tid];

    int row0 = blockIdx.x * 128, n0 = blockIdx.y * 128;
    float acc[2][8][4];
#pragma unroll
    for (int mt = 0; mt < 2; mt++)
#pragma unroll
        for (int nt = 0; nt < 8; nt++)
#pragma unroll
            for (int q = 0; q < 4; q++) acc[mt][nt][q] = 0.f;

    mma_mainloop(sb, A, Bth, Btl, row0, n0, M, K, acc);

    int lane = tid & 31, wid = tid >> 5;
    int g = lane >> 2, tig = lane & 3;
    int wm = wid & 3, wn = wid >> 2;
#pragma unroll
    for (int mt = 0; mt < 2; mt++) {
        int r0 = row0 + wm * 32 + mt * 16 + g;
#pragma unroll
        for (int nt = 0; nt < 8; nt++) {
            int cc = n0 + wn * 64 + nt * 8 + 2 * tig;
            float b0 = bsm[cc], b1 = bsm[cc + 1];
            float* d = acc[mt][nt];
            if (r0 < M)
                *(float2*)(Cout + (size_t)r0 * 512 + cc) = make_float2(d[0] + b0, d[1] + b1);
            if (r0 + 8 < M)
                *(float2*)(Cout + (size_t)(r0 + 8) * 512 + cc) = make_float2(d[2] + b0, d[3] + b1);
        }
    }
}

// ---------------- edge GEMM fused epilogue ----------------
__global__ __launch_bounds__(256, 2) void gemm_edge_mma(
    const float* __restrict__ A,
    const __nv_bfloat16* __restrict__ Bth, const __nv_bfloat16* __restrict__ Btl,
    const float* __restrict__ node_out,
    const int* __restrict__ src, const int* __restrict__ dst,
    const float* __restrict__ bias, const float* __restrict__ attn,
    float* __restrict__ ef_out, float* __restrict__ elog,
    unsigned* __restrict__ menc, int M, int K) {
    extern __shared__ __align__(16) char smem[];
    uint32_t sb = smem_u32(smem);
    float* stage = (float*)(smem + EST);     // overlaps tile buffers
    int*   ssh = (int*)(smem + ESRC);
    int*   dsh = (int*)(smem + EDST);
    float* bsh = (float*)(smem + EBIAS);
    float* ash = (float*)(smem + EATTN);
    float* lsh = (float*)(smem + ELSH);

    int tid = threadIdx.x;
    int e0 = blockIdx.x * 128;
    if (tid < 128) {
        int e = e0 + tid;
        ssh[tid] = (e < M) ? src[e] : 0;
        dsh[tid] = (e < M) ? dst[e] : 0;
        bsh[tid] = bias[tid];
        ash[tid] = attn[tid];
    }

    float acc[2][8][4];
#pragma unroll
    for (int mt = 0; mt < 2; mt++)
#pragma unroll
        for (int nt = 0; nt < 8; nt++)
#pragma unroll
            for (int q = 0; q < 4; q++) acc[mt][nt][q] = 0.f;

    mma_mainloop(sb, A, Bth, Btl, e0, 0, M, K, acc);
    // mainloop ends with __syncthreads(); tile buffers now reusable as stage

    int lane = tid & 31, wid = tid >> 5;
    int g = lane >> 2, tig = lane & 3;
    int wm = wid & 3, wn = wid >> 2;
#pragma unroll
    for (int mt = 0; mt < 2; mt++) {
        int r = wm * 32 + mt * 16 + g;
#pragma unroll
        for (int nt = 0; nt < 8; nt++) {
            int cc = wn * 64 + nt * 8 + 2 * tig;
            float* d = acc[mt][nt];
            *(float2*)&stage[r * 132 + cc] = make_float2(d[0], d[1]);
            *(float2*)&stage[(r + 8) * 132 + cc] = make_float2(d[2], d[3]);
        }
    }
    __syncthreads();

    {
        int r = tid & 127, hc = tid >> 7;
        int e = e0 + r;
        if (e < M) {
            int si = ssh[r], dj = dsh[r];
            const float* pni = node_out + (size_t)si * 512 + hc * 64;
            const float* pnj = node_out + (size_t)dj * 512 + 128 + hc * 64;
            const float* sp = stage + r * 132 + hc * 64;
            float* op = ef_out + (size_t)e * 128 + hc * 64;
            float part[2] = {0.f, 0.f};
#pragma unroll
            for (int q = 0; q < 16; q++) {
                int c = hc * 64 + q * 4;
                float4 sv = *(const float4*)(sp + q * 4);
                float4 a = *(const float4*)(pni + q * 4);
                float4 b = *(const float4*)(pnj + q * 4);
                float4 o;
                float v;
                v = sv.x + a.x + b.x + bsh[c + 0];
                v = lrelu_f(v); part[q >> 3] += v * ash[c + 0]; o.x = elu_f(v);
                v = sv.y + a.y + b.y + bsh[c + 1];
                v = lrelu_f(v); part[q >> 3] += v * ash[c + 1]; o.y = elu_f(v);
                v = sv.z + a.z + b.z + bsh[c + 2];
                v = lrelu_f(v); part[q >> 3] += v * ash[c + 2]; o.z = elu_f(v);
                v = sv.w + a.w + b.w + bsh[c + 3];
                v = lrelu_f(v); part[q >> 3] += v * ash[c + 3]; o.w = elu_f(v);
                *(float4*)(op + q * 4) = o;
            }
            lsh[r * 4 + hc * 2 + 0] = part[0];
            lsh[r * 4 + hc * 2 + 1] = part[1];
        }
    }
    __syncthreads();

    for (int t = tid; t < 512; t += 256) {
        int r2 = t >> 2, h = t & 3;
        int e2 = e0 + r2;
        if (e2 < M) {
            float lg = lsh[r2 * 4 + h];
            elog[(size_t)e2 * 4 + h] = lg;
            atomicMax(&menc[(size_t)dsh[r2] * 4 + h], fenc(lg));
        }
    }
}

// ---------------- segment softmax denom ----------------
__global__ void k_expsum(const int* __restrict__ dst, float* __restrict__ elog,
                         const unsigned* __restrict__ menc, float* __restrict__ s) {
    int e = blockIdx.x * 256 + threadIdx.x;
    if (e < EE) {
        int d = dst[e];
        float4 l = *(const float4*)(elog + (size_t)e * 4);
        float m0 = fdec(menc[(size_t)d * 4 + 0]);
        float m1 = fdec(menc[(size_t)d * 4 + 1]);
        float m2 = fdec(menc[(size_t)d * 4 + 2]);
        float m3 = fdec(menc[(size_t)d * 4 + 3]);
        float4 ee = make_float4(expf(l.x - m0), expf(l.y - m1),
                                expf(l.z - m2), expf(l.w - m3));
        red4(&s[(size_t)d * 4], ee);
        *(float4*)(elog + (size_t)e * 4) = ee;
    }
}

// ---------------- message aggregation ----------------
__global__ __launch_bounds__(256) void k_msg(
    const int* __restrict__ src, const int* __restrict__ dst,
    const float* __restrict__ elog, const float* __restrict__ s,
    const float* __restrict__ node_out, float* __restrict__ hnew) {
    int e = blockIdx.x * 4 + (threadIdx.x >> 6);
    int q = threadIdx.x & 63;
    if (e < EE) {
        int si = src[e], di = dst[e];
        int h = q >> 4;
        float alpha = elog[(size_t)e * 4 + h] / s[(size_t)di * 4 + h];
        float4 v = *(const float4*)(node_out + (size_t)si * 512 + 256 + q * 4);
        red4(&hnew[(size_t)di * 256 + q * 4],
             make_float4(v.x * alpha, v.y * alpha, v.z * alpha, v.w * alpha));
    }
}

// ---------------- host ----------------
extern "C" void kernel_launch(void* const* d_in, const int* in_sizes, int n_in,
                              void* d_out, int out_size) {
    const int*   node_types = (const int*)d_in[0];
    const int*   src        = (const int*)d_in[1];
    const int*   dst        = (const int*)d_in[2];
    const float* efeats     = (const float*)d_in[3];
    const float* embed      = (const float*)d_in[4];
    const float* W_src[2] = {(const float*)d_in[5],  (const float*)d_in[12]};
    const float* b_src[2] = {(const float*)d_in[6],  (const float*)d_in[13]};
    const float* W_ni[2]  = {(const float*)d_in[7],  (const float*)d_in[14]};
    const float* W_nj[2]  = {(const float*)d_in[8],  (const float*)d_in[15]};
    const float* W_fij[2] = {(const float*)d_in[9],  (const float*)d_in[16]};
    const float* attn[2]  = {(const float*)d_in[10], (const float*)d_in[17]};
    const float* bias[2]  = {(const float*)d_in[11], (const float*)d_in[18]};

    float *nf, *node_out, *efbuf, *elog, *s, *hnew, *bcat;
    unsigned* menc;
    __nv_bfloat16 *btnh, *btnl, *bteh, *btel;
    cudaGetSymbolAddress((void**)&nf, g_nf);
    cudaGetSymbolAddress((void**)&node_out, g_node_out);
    cudaGetSymbolAddress((void**)&efbuf, g_efbuf);
    cudaGetSymbolAddress((void**)&elog, g_elog);
    cudaGetSymbolAddress((void**)&menc, g_menc);
    cudaGetSymbolAddress((void**)&s, g_s);
    cudaGetSymbolAddress((void**)&hnew, g_hnew);
    cudaGetSymbolAddress((void**)&bcat, g_bcat);
    cudaGetSymbolAddress((void**)&btnh, g_btn_hi);
    cudaGetSymbolAddress((void**)&btnl, g_btn_lo);
    cudaGetSymbolAddress((void**)&bteh, g_bte_hi);
    cudaGetSymbolAddress((void**)&btel, g_bte_lo);

    cudaFuncSetAttribute(gemm_node_mma, cudaFuncAttributeMaxDynamicSharedMemorySize, NODE_SMEM);
    cudaFuncSetAttribute(gemm_edge_mma, cudaFuncAttributeMaxDynamicSharedMemorySize, EDGE_SMEM);

    float* out_nf = (float*)d_out;
    float* out_ef = out_nf + (size_t)NN * 256;

    k_embed<<<(NN * 128 + 255) / 256, 256>>>(node_types, embed, nf);

    const float* ef_in = efeats;
    for (int L = 0; L < 2; L++) {
        int in_n = L ? 256 : 128;
        int in_e = L ? 128 : 64;
        int prep_items = 512 * in_n + 128 * in_e;
        k_prep<<<(prep_items + 255) / 256, 256>>>(W_ni[L], W_nj[L], W_src[L], b_src[L],
                                                  W_fij[L], bcat, btnh, btnl, bteh, btel,
                                                  in_n, in_e);
        k_clear<<<(NN * 256 + 255) / 256, 256>>>(menc, s, hnew);

        dim3 gn((NN + 127) / 128, 4);
        gemm_node_mma<<<gn, 256, NODE_SMEM>>>(nf, btnh, btnl, bcat, node_out, NN, in_n);

        float* ef_out = L ? out_ef : efbuf;
        gemm_edge_mma<<<(EE + 127) / 128, 256, EDGE_SMEM>>>(ef_in, bteh, btel, node_out,
                                                            src, dst, bias[L], attn[L],
                                                            ef_out, elog, menc, EE, in_e);
        k_expsum<<<(EE + 255) / 256, 256>>>(dst, elog, menc, s);
        k_msg<<<EE / 4, 256>>>(src, dst, elog, s, node_out, hnew);

        float* nf_out = L ? out_nf : nf;
        k_elu<<<(NN * 256 + 255) / 256, 256>>>(hnew, nf_out, NN * 256);
        ef_in = ef_out;
    }
}

// round 5
// speedup vs baseline: 1.6737x; 1.2714x over previous
#include <cuda_runtime.h>
#include <cuda_bf16.h>
#include <math.h>
#include <stdint.h>

#define NN 50000
#define EE 500000
#define NB_SCAN ((NN + 255) / 256)   // 196

// ---------------- scratch ----------------
__device__ float    g_nf[(size_t)NN * 256];
__device__ float    g_node_out[(size_t)NN * 512];  // [f_ni(128) | f_nj(128) | h_src(256)]
__device__ float    g_efbuf[(size_t)EE * 128];
__device__ float    g_elog[(size_t)EE * 4];        // raw attention logits
__device__ float    g_bcat[512];
__device__ __nv_bfloat16 g_btn_hi[512 * 256];
__device__ __nv_bfloat16 g_btn_lo[512 * 256];
__device__ __nv_bfloat16 g_bte_hi[128 * 128];
__device__ __nv_bfloat16 g_bte_lo[128 * 128];
// CSR by dst
__device__ int g_deg[NN];
__device__ int g_offs[NN + 1];
__device__ int g_cursor[NN];
__device__ int g_eidx[EE];
__device__ int g_bsum[256];

// ---------------- helpers ----------------
__device__ __forceinline__ uint32_t smem_u32(const void* p) {
    uint32_t a;
    asm("{ .reg .u64 t; cvta.to.shared.u64 t, %1; cvt.u32.u64 %0, t; }" : "=r"(a) : "l"(p));
    return a;
}
__device__ __forceinline__ unsigned lds32(uint32_t a) {
    unsigned v;
    asm volatile("ld.shared.b32 %0, [%1];" : "=r"(v) : "r"(a));
    return v;
}
__device__ __forceinline__ void sts128(uint32_t a, uint4 v) {
    asm volatile("st.shared.v4.b32 [%0], {%1, %2, %3, %4};"
                 :: "r"(a), "r"(v.x), "r"(v.y), "r"(v.z), "r"(v.w) : "memory");
}
#define CP_ASYNC16(dst, src) \
    asm volatile("cp.async.ca.shared.global [%0], [%1], 16;" :: "r"(dst), "l"(src) : "memory")
#define CP_COMMIT() asm volatile("cp.async.commit_group;" ::: "memory")
#define CP_WAIT0()  asm volatile("cp.async.wait_group 0;" ::: "memory")

__device__ __forceinline__ void mma_bf16(float& d0, float& d1, float& d2, float& d3,
                                         unsigned a0, unsigned a1, unsigned a2, unsigned a3,
                                         unsigned b0, unsigned b1) {
    asm volatile(
        "mma.sync.aligned.m16n8k16.row.col.f32.bf16.bf16.f32 "
        "{%0,%1,%2,%3}, {%4,%5,%6,%7}, {%8,%9}, {%0,%1,%2,%3};"
        : "+f"(d0), "+f"(d1), "+f"(d2), "+f"(d3)
        : "r"(a0), "r"(a1), "r"(a2), "r"(a3), "r"(b0), "r"(b1));
}
__device__ __forceinline__ void split2(float a, float b, unsigned& hi, unsigned& lo) {
    __nv_bfloat16 ah = __float2bfloat16_rn(a), bh = __float2bfloat16_rn(b);
    __nv_bfloat16 al = __float2bfloat16_rn(a - __bfloat162float(ah));
    __nv_bfloat16 bl = __float2bfloat16_rn(b - __bfloat162float(bh));
    hi = (unsigned)__bfloat16_as_ushort(ah) | ((unsigned)__bfloat16_as_ushort(bh) << 16);
    lo = (unsigned)__bfloat16_as_ushort(al) | ((unsigned)__bfloat16_as_ushort(bl) << 16);
}
__device__ __forceinline__ float elu_f(float v)   { return v > 0.f ? v : expm1f(v); }
__device__ __forceinline__ float lrelu_f(float v) { return v > 0.f ? v : 0.01f * v; }

// ---------------- smem layout (bytes) ----------------
#define AHI    0
#define ALO    10240
#define BHI    20480
#define BLO    30720
#define BUFSZ  40960
#define TILES_END 81920
#define NODE_BIAS 81920
#define NODE_SMEM (81920 + 2048)
#define EST      0
#define ESRC     81920
#define EDST     82432
#define EBIAS    82944
#define EATTN    83456
#define ELSH     83968
#define EDGE_SMEM 86016

// ---------------- small kernels ----------------
__global__ void k_embed(const int* __restrict__ node_types,
                        const float* __restrict__ embed, float* __restrict__ nf) {
    int i = blockIdx.x * 256 + threadIdx.x;
    if (i < NN * 128) {
        int n = i >> 7, c = i & 127;
        nf[(size_t)n * 128 + c] = embed[node_types[n] * 128 + c];
    }
}

__global__ void k_prep(const float* __restrict__ Wni, const float* __restrict__ Wnj,
                       const float* __restrict__ Wsrc, const float* __restrict__ bsrc,
                       const float* __restrict__ Wfij,
                       float* __restrict__ bcat,
                       __nv_bfloat16* __restrict__ btn_hi, __nv_bfloat16* __restrict__ btn_lo,
                       __nv_bfloat16* __restrict__ bte_hi, __nv_bfloat16* __restrict__ bte_lo,
                       int in_n, int in_e) {
    int i = blockIdx.x * 256 + threadIdx.x;
    int nn = 512 * in_n;
    if (i < nn) {
        int n = i / in_n, k = i - n * in_n;
        float v;
        if (n < 128)      v = Wni[k * 128 + n];
        else if (n < 256) v = Wnj[k * 128 + (n - 128)];
        else              v = Wsrc[k * 256 + (n - 256)];
        __nv_bfloat16 h = __float2bfloat16_rn(v);
        __nv_bfloat16 l = __float2bfloat16_rn(v - __bfloat162float(h));
        btn_hi[(size_t)n * in_n + k] = h;
        btn_lo[(size_t)n * in_n + k] = l;
    } else if (i < nn + 128 * in_e) {
        int j = i - nn;
        int n = j / in_e, k = j - n * in_e;
        float v = Wfij[k * 128 + n];
        __nv_bfloat16 h = __float2bfloat16_rn(v);
        __nv_bfloat16 l = __float2bfloat16_rn(v - __bfloat162float(h));
        bte_hi[(size_t)n * in_e + k] = h;
        bte_lo[(size_t)n * in_e + k] = l;
    }
    if (i < 512) bcat[i] = (i < 256) ? 0.f : bsrc[i - 256];
}

// ---------------- CSR build ----------------
__global__ void k_zero_deg(int* __restrict__ deg) {
    int i = blockIdx.x * 256 + threadIdx.x;
    if (i < NN) deg[i] = 0;
}
__global__ void k_hist(const int* __restrict__ dst, int* __restrict__ deg) {
    int e = blockIdx.x * 256 + threadIdx.x;
    if (e < EE) atomicAdd(&deg[dst[e]], 1);
}
__global__ void k_scanA(const int* __restrict__ deg, int* __restrict__ bsum) {
    __shared__ int sh[256];
    int i = blockIdx.x * 256 + threadIdx.x;
    sh[threadIdx.x] = (i < NN) ? deg[i] : 0;
    __syncthreads();
    for (int o = 128; o > 0; o >>= 1) {
        if (threadIdx.x < o) sh[threadIdx.x] += sh[threadIdx.x + o];
        __syncthreads();
    }
    if (threadIdx.x == 0) bsum[blockIdx.x] = sh[0];
}
__global__ void k_scanB(int* __restrict__ bsum) {
    __shared__ int sh[256];
    int t = threadIdx.x;
    int v = (t < NB_SCAN) ? bsum[t] : 0;
    sh[t] = v;
    __syncthreads();
    for (int o = 1; o < 256; o <<= 1) {
        int add = (t >= o) ? sh[t - o] : 0;
        __syncthreads();
        sh[t] += add;
        __syncthreads();
    }
    if (t < NB_SCAN) bsum[t] = sh[t] - v;  // exclusive
}
__global__ void k_scanC(const int* __restrict__ deg, const int* __restrict__ bsum,
                        int* __restrict__ offs, int* __restrict__ cursor) {
    __shared__ int sh[256];
    int i = blockIdx.x * 256 + threadIdx.x;
    int t = threadIdx.x;
    int v = (i < NN) ? deg[i] : 0;
    sh[t] = v;
    __syncthreads();
    for (int o = 1; o < 256; o <<= 1) {
        int add = (t >= o) ? sh[t - o] : 0;
        __syncthreads();
        sh[t] += add;
        __syncthreads();
    }
    if (i < NN) {
        int ex = bsum[blockIdx.x] + sh[t] - v;
        offs[i] = ex;
        cursor[i] = ex;
    }
    if (i == 0) offs[NN] = EE;
}
__global__ void k_scatter(const int* __restrict__ dst, int* __restrict__ cursor,
                          int* __restrict__ eidx) {
    int e = blockIdx.x * 256 + threadIdx.x;
    if (e < EE) {
        int pos = atomicAdd(&cursor[dst[e]], 1);
        eidx[pos] = e;
    }
}

// ---------------- pipelined GEMM mainloop ----------------
__device__ __forceinline__ void b_cpasync(uint32_t sb, int buf,
                                          const __nv_bfloat16* __restrict__ Bth,
                                          const __nv_bfloat16* __restrict__ Btl,
                                          int n0, int K, int k0) {
    int tid = threadIdx.x;
#pragma unroll
    for (int i = 0; i < 2; i++) {
        int c = tid + i * 256;
        int n = c >> 2, k16 = c & 3;
        size_t go = (size_t)(n0 + n) * K + k0 + k16 * 8;
        uint32_t da = sb + buf * BUFSZ + BHI + n * 80 + k16 * 16;
        CP_ASYNC16(da, Bth + go);
        CP_ASYNC16(da + (BLO - BHI), Btl + go);
    }
}

__device__ __forceinline__ void a_convert_sts(uint32_t sb, int buf, int r, int hk,
                                              const float4 pa[4]) {
    uint32_t ah = sb + buf * BUFSZ + AHI + r * 80 + hk * 32;
    uint32_t al = ah + (ALO - AHI);
#pragma unroll
    for (int q = 0; q < 2; q++) {
        unsigned h0, l0, h1, l1, h2, l2, h3, l3;
        split2(pa[2 * q].x,     pa[2 * q].y,     h0, l0);
        split2(pa[2 * q].z,     pa[2 * q].w,     h1, l1);
        split2(pa[2 * q + 1].x, pa[2 * q + 1].y, h2, l2);
        split2(pa[2 * q + 1].z, pa[2 * q + 1].w, h3, l3);
        sts128(ah + q * 16, make_uint4(h0, h1, h2, h3));
        sts128(al + q * 16, make_uint4(l0, l1, l2, l3));
    }
}

__device__ __forceinline__ void mma_compute(uint32_t sb, int buf, float acc[2][8][4]) {
    int tid = threadIdx.x, lane = tid & 31, wid = tid >> 5;
    int g = lane >> 2, tig = lane & 3;
    int wm = wid & 3, wn = wid >> 2;
    uint32_t bo = sb + buf * BUFSZ;
#pragma unroll
    for (int ks = 0; ks < 2; ks++) {
        unsigned ahr[2][4], alr[2][4];
        uint32_t abase = bo + AHI + (wm * 32 + g) * 80 + ks * 32 + tig * 4;
#pragma unroll
        for (int mt = 0; mt < 2; mt++) {
            uint32_t a0 = abase + mt * (16 * 80);
            ahr[mt][0] = lds32(a0);
            ahr[mt][1] = lds32(a0 + 8 * 80);
            ahr[mt][2] = lds32(a0 + 16);
            ahr[mt][3] = lds32(a0 + 8 * 80 + 16);
            uint32_t a0l = a0 + (ALO - AHI);
            alr[mt][0] = lds32(a0l);
            alr[mt][1] = lds32(a0l + 8 * 80);
            alr[mt][2] = lds32(a0l + 16);
            alr[mt][3] = lds32(a0l + 8 * 80 + 16);
        }
        uint32_t bbase = bo + BHI + (wn * 64 + g) * 80 + ks * 32 + tig * 4;
#pragma unroll
        for (int nt = 0; nt < 8; nt++) {
            uint32_t b0a = bbase + nt * (8 * 80);
            unsigned bh0 = lds32(b0a), bh1 = lds32(b0a + 16);
            unsigned bl0 = lds32(b0a + (BLO - BHI)), bl1 = lds32(b0a + (BLO - BHI) + 16);
#pragma unroll
            for (int mt = 0; mt < 2; mt++) {
                float* d = acc[mt][nt];
                mma_bf16(d[0], d[1], d[2], d[3],
                         ahr[mt][0], ahr[mt][1], ahr[mt][2], ahr[mt][3], bh0, bh1);
                mma_bf16(d[0], d[1], d[2], d[3],
                         ahr[mt][0], ahr[mt][1], ahr[mt][2], ahr[mt][3], bl0, bl1);
                mma_bf16(d[0], d[1], d[2], d[3],
                         alr[mt][0], alr[mt][1], alr[mt][2], alr[mt][3], bh0, bh1);
            }
        }
    }
}

__device__ __forceinline__ void mma_mainloop(
    uint32_t sb, const float* __restrict__ A,
    const __nv_bfloat16* __restrict__ Bth, const __nv_bfloat16* __restrict__ Btl,
    int row0, int n0, int M, int K, float acc[2][8][4]) {
    int tid = threadIdx.x;
    int r = tid >> 1, hk = tid & 1;
    int arow = row0 + r;
    bool aval = arow < M;
    const float* abase = A + (size_t)arow * K + hk * 16;
    int nst = K >> 5;

    float4 pa[4];
    const float4 z4 = make_float4(0.f, 0.f, 0.f, 0.f);
#pragma unroll
    for (int q = 0; q < 4; q++) pa[q] = aval ? *(const float4*)(abase + q * 4) : z4;
    b_cpasync(sb, 0, Bth, Btl, n0, K, 0);
    CP_COMMIT();
    a_convert_sts(sb, 0, r, hk, pa);
    CP_WAIT0();
    __syncthreads();

    for (int s = 0; s < nst; s++) {
        int buf = s & 1, nb = buf ^ 1;
        bool more = (s + 1) < nst;
        if (more) {
            b_cpasync(sb, nb, Bth, Btl, n0, K, (s + 1) * 32);
            CP_COMMIT();
            const float* ap = abase + (s + 1) * 32;
#pragma unroll
            for (int q = 0; q < 4; q++) pa[q] = aval ? *(const float4*)(ap + q * 4) : z4;
        }
        mma_compute(sb, buf, acc);
        if (more) {
            a_convert_sts(sb, nb, r, hk, pa);
            CP_WAIT0();
        }
        __syncthreads();
    }
}

// ---------------- node GEMM ----------------
__global__ __launch_bounds__(256, 2) void gemm_node_mma(
    const float* __restrict__ A,
    const __nv_bfloat16* __restrict__ Bth, const __nv_bfloat16* __restrict__ Btl,
    const float* __restrict__ bias, float* __restrict__ Cout, int M, int K) {
    extern __shared__ __align__(16) char smem[];
    uint32_t sb = smem_u32(smem);
    float* bsm = (float*)(smem + NODE_BIAS);
    int tid = threadIdx.x;
    ((float2*)bsm)[tid] = ((const float2*)bias)[tid];

    int row0 = blockIdx.x * 128, n0 = blockIdx.y * 128;
    float acc[2][8][4];
#pragma unroll
    for (int mt = 0; mt < 2; mt++)
#pragma unroll
        for (int nt = 0; nt < 8; nt++)
#pragma unroll
            for (int q = 0; q < 4; q++) acc[mt][nt][q] = 0.f;

    mma_mainloop(sb, A, Bth, Btl, row0, n0, M, K, acc);

    int lane = tid & 31, wid = tid >> 5;
    int g = lane >> 2, tig = lane & 3;
    int wm = wid & 3, wn = wid >> 2;
#pragma unroll
    for (int mt = 0; mt < 2; mt++) {
        int r0 = row0 + wm * 32 + mt * 16 + g;
#pragma unroll
        for (int nt = 0; nt < 8; nt++) {
            int cc = n0 + wn * 64 + nt * 8 + 2 * tig;
            float b0 = bsm[cc], b1 = bsm[cc + 1];
            float* d = acc[mt][nt];
            if (r0 < M)
                *(float2*)(Cout + (size_t)r0 * 512 + cc) = make_float2(d[0] + b0, d[1] + b1);
            if (r0 + 8 < M)
                *(float2*)(Cout + (size_t)(r0 + 8) * 512 + cc) = make_float2(d[2] + b0, d[3] + b1);
        }
    }
}

// ---------------- edge GEMM fused epilogue (writes raw logits) ----------------
__global__ __launch_bounds__(256, 2) void gemm_edge_mma(
    const float* __restrict__ A,
    const __nv_bfloat16* __restrict__ Bth, const __nv_bfloat16* __restrict__ Btl,
    const float* __restrict__ node_out,
    const int* __restrict__ src, const int* __restrict__ dst,
    const float* __restrict__ bias, const float* __restrict__ attn,
    float* __restrict__ ef_out, float* __restrict__ elog, int M, int K) {
    extern __shared__ __align__(16) char smem[];
    uint32_t sb = smem_u32(smem);
    float* stage = (float*)(smem + EST);
    int*   ssh = (int*)(smem + ESRC);
    int*   dsh = (int*)(smem + EDST);
    float* bsh = (float*)(smem + EBIAS);
    float* ash = (float*)(smem + EATTN);
    float* lsh = (float*)(smem + ELSH);

    int tid = threadIdx.x;
    int e0 = blockIdx.x * 128;
    if (tid < 128) {
        int e = e0 + tid;
        ssh[tid] = (e < M) ? src[e] : 0;
        dsh[tid] = (e < M) ? dst[e] : 0;
        bsh[tid] = bias[tid];
        ash[tid] = attn[tid];
    }

    float acc[2][8][4];
#pragma unroll
    for (int mt = 0; mt < 2; mt++)
#pragma unroll
        for (int nt = 0; nt < 8; nt++)
#pragma unroll
            for (int q = 0; q < 4; q++) acc[mt][nt][q] = 0.f;

    mma_mainloop(sb, A, Bth, Btl, e0, 0, M, K, acc);

    int lane = tid & 31, wid = tid >> 5;
    int g = lane >> 2, tig = lane & 3;
    int wm = wid & 3, wn = wid >> 2;
#pragma unroll
    for (int mt = 0; mt < 2; mt++) {
        int r = wm * 32 + mt * 16 + g;
#pragma unroll
        for (int nt = 0; nt < 8; nt++) {
            int cc = wn * 64 + nt * 8 + 2 * tig;
            float* d = acc[mt][nt];
            *(float2*)&stage[r * 132 + cc] = make_float2(d[0], d[1]);
            *(float2*)&stage[(r + 8) * 132 + cc] = make_float2(d[2], d[3]);
        }
    }
    __syncthreads();

    {
        int r = tid & 127, hc = tid >> 7;
        int e = e0 + r;
        if (e < M) {
            int si = ssh[r], dj = dsh[r];
            const float* pni = node_out + (size_t)si * 512 + hc * 64;
            const float* pnj = node_out + (size_t)dj * 512 + 128 + hc * 64;
            const float* sp = stage + r * 132 + hc * 64;
            float* op = ef_out + (size_t)e * 128 + hc * 64;
            float part[2] = {0.f, 0.f};
#pragma unroll
            for (int q = 0; q < 16; q++) {
                int c = hc * 64 + q * 4;
                float4 sv = *(const float4*)(sp + q * 4);
                float4 a = *(const float4*)(pni + q * 4);
                float4 b = *(const float4*)(pnj + q * 4);
                float4 o;
                float v;
                v = sv.x + a.x + b.x + bsh[c + 0];
                v = lrelu_f(v); part[q >> 3] += v * ash[c + 0]; o.x = elu_f(v);
                v = sv.y + a.y + b.y + bsh[c + 1];
                v = lrelu_f(v); part[q >> 3] += v * ash[c + 1]; o.y = elu_f(v);
                v = sv.z + a.z + b.z + bsh[c + 2];
                v = lrelu_f(v); part[q >> 3] += v * ash[c + 2]; o.z = elu_f(v);
                v = sv.w + a.w + b.w + bsh[c + 3];
                v = lrelu_f(v); part[q >> 3] += v * ash[c + 3]; o.w = elu_f(v);
                *(float4*)(op + q * 4) = o;
            }
            lsh[r * 4 + hc * 2 + 0] = part[0];
            lsh[r * 4 + hc * 2 + 1] = part[1];
        }
    }
    __syncthreads();

    for (int t = tid; t < 512; t += 256) {
        int r2 = t >> 2, h = t & 3;
        int e2 = e0 + r2;
        if (e2 < M) elog[(size_t)e2 * 4 + h] = lsh[r2 * 4 + h];
    }
}

// ---------------- CSR aggregation: softmax + message sum + ELU ----------------
__global__ __launch_bounds__(256) void k_aggr(
    const int* __restrict__ srcs, const int* __restrict__ eidx,
    const int* __restrict__ offs, const float* __restrict__ elog,
    const float* __restrict__ node_out, float* __restrict__ outp) {
    int node = (blockIdx.x * 256 + threadIdx.x) >> 5;
    int lane = threadIdx.x & 31;
    if (node >= NN) return;
    int beg = offs[node], end = offs[node + 1];

    // pass 1: per-head max (strided over lanes, then warp-reduce)
    float4 mx = make_float4(-1e30f, -1e30f, -1e30f, -1e30f);
    for (int j = beg + lane; j < end; j += 32) {
        int e = eidx[j];
        float4 l = *(const float4*)(elog + (size_t)e * 4);
        mx.x = fmaxf(mx.x, l.x); mx.y = fmaxf(mx.y, l.y);
        mx.z = fmaxf(mx.z, l.z); mx.w = fmaxf(mx.w, l.w);
    }
#pragma unroll
    for (int o = 16; o > 0; o >>= 1) {
        mx.x = fmaxf(mx.x, __shfl_xor_sync(0xFFFFFFFFu, mx.x, o));
        mx.y = fmaxf(mx.y, __shfl_xor_sync(0xFFFFFFFFu, mx.y, o));
        mx.z = fmaxf(mx.z, __shfl_xor_sync(0xFFFFFFFFu, mx.z, o));
        mx.w = fmaxf(mx.w, __shfl_xor_sync(0xFFFFFFFFu, mx.w, o));
    }
    int h = lane >> 3;  // this lane's head (owns cols [lane*8, lane*8+8))
    float mh = (h == 0) ? mx.x : (h == 1) ? mx.y : (h == 2) ? mx.z : mx.w;

    // pass 2: accumulate w * h_src
    float acc[8] = {0.f, 0.f, 0.f, 0.f, 0.f, 0.f, 0.f, 0.f};
    float ssum = 0.f;
    for (int j = beg; j < end; j++) {
        int e = eidx[j];
        float w = expf(elog[(size_t)e * 4 + h] - mh);
        ssum += w;
        const float4* hp = (const float4*)(node_out + (size_t)srcs[e] * 512 + 256) + lane * 2;
        float4 v0 = hp[0], v1 = hp[1];
        acc[0] += w * v0.x; acc[1] += w * v0.y; acc[2] += w * v0.z; acc[3] += w * v0.w;
        acc[4] += w * v1.x; acc[5] += w * v1.y; acc[6] += w * v1.z; acc[7] += w * v1.w;
    }
    float inv = (end > beg) ? 1.f / ssum : 0.f;
    float* op = outp + (size_t)node * 256 + lane * 8;
    float4 o0, o1;
    o0.x = elu_f(acc[0] * inv); o0.y = elu_f(acc[1] * inv);
    o0.z = elu_f(acc[2] * inv); o0.w = elu_f(acc[3] * inv);
    o1.x = elu_f(acc[4] * inv); o1.y = elu_f(acc[5] * inv);
    o1.z = elu_f(acc[6] * inv); o1.w = elu_f(acc[7] * inv);
    *(float4*)op = o0;
    *(float4*)(op + 4) = o1;
}

// ---------------- host ----------------
extern "C" void kernel_launch(void* const* d_in, const int* in_sizes, int n_in,
                              void* d_out, int out_size) {
    const int*   node_types = (const int*)d_in[0];
    const int*   src        = (const int*)d_in[1];
    const int*   dst        = (const int*)d_in[2];
    const float* efeats     = (const float*)d_in[3];
    const float* embed      = (const float*)d_in[4];
    const float* W_src[2] = {(const float*)d_in[5],  (const float*)d_in[12]};
    const float* b_src[2] = {(const float*)d_in[6],  (const float*)d_in[13]};
    const float* W_ni[2]  = {(const float*)d_in[7],  (const float*)d_in[14]};
    const float* W_nj[2]  = {(const float*)d_in[8],  (const float*)d_in[15]};
    const float* W_fij[2] = {(const float*)d_in[9],  (const float*)d_in[16]};
    const float* attn[2]  = {(const float*)d_in[10], (const float*)d_in[17]};
    const float* bias[2]  = {(const float*)d_in[11], (const float*)d_in[18]};

    float *nf, *node_out, *efbuf, *elog, *bcat;
    int *deg, *offs, *cursor, *eidx, *bsum;
    __nv_bfloat16 *btnh, *btnl, *bteh, *btel;
    cudaGetSymbolAddress((void**)&nf, g_nf);
    cudaGetSymbolAddress((void**)&node_out, g_node_out);
    cudaGetSymbolAddress((void**)&efbuf, g_efbuf);
    cudaGetSymbolAddress((void**)&elog, g_elog);
    cudaGetSymbolAddress((void**)&bcat, g_bcat);
    cudaGetSymbolAddress((void**)&btnh, g_btn_hi);
    cudaGetSymbolAddress((void**)&btnl, g_btn_lo);
    cudaGetSymbolAddress((void**)&bteh, g_bte_hi);
    cudaGetSymbolAddress((void**)&btel, g_bte_lo);
    cudaGetSymbolAddress((void**)&deg, g_deg);
    cudaGetSymbolAddress((void**)&offs, g_offs);
    cudaGetSymbolAddress((void**)&cursor, g_cursor);
    cudaGetSymbolAddress((void**)&eidx, g_eidx);
    cudaGetSymbolAddress((void**)&bsum, g_bsum);

    cudaFuncSetAttribute(gemm_node_mma, cudaFuncAttributeMaxDynamicSharedMemorySize, NODE_SMEM);
    cudaFuncSetAttribute(gemm_edge_mma, cudaFuncAttributeMaxDynamicSharedMemorySize, EDGE_SMEM);

    float* out_nf = (float*)d_out;
    float* out_ef = out_nf + (size_t)NN * 256;

    k_embed<<<(NN * 128 + 255) / 256, 256>>>(node_types, embed, nf);

    // CSR by dst (edges identical across layers; build once)
    k_zero_deg<<<NB_SCAN, 256>>>(deg);
    k_hist<<<(EE + 255) / 256, 256>>>(dst, deg);
    k_scanA<<<NB_SCAN, 256>>>(deg, bsum);
    k_scanB<<<1, 256>>>(bsum);
    k_scanC<<<NB_SCAN, 256>>>(deg, bsum, offs, cursor);
    k_scatter<<<(EE + 255) / 256, 256>>>(dst, cursor, eidx);

    const float* ef_in = efeats;
    for (int L = 0; L < 2; L++) {
        int in_n = L ? 256 : 128;
        int in_e = L ? 128 : 64;
        int prep_items = 512 * in_n + 128 * in_e;
        k_prep<<<(prep_items + 255) / 256, 256>>>(W_ni[L], W_nj[L], W_src[L], b_src[L],
                                                  W_fij[L], bcat, btnh, btnl, bteh, btel,
                                                  in_n, in_e);

        dim3 gn((NN + 127) / 128, 4);
        gemm_node_mma<<<gn, 256, NODE_SMEM>>>(nf, btnh, btnl, bcat, node_out, NN, in_n);

        float* ef_out = L ? out_ef : efbuf;
        gemm_edge_mma<<<(EE + 127) / 128, 256, EDGE_SMEM>>>(ef_in, bteh, btel, node_out,
                                                            src, dst, bias[L], attn[L],
                                                            ef_out, elog, EE, in_e);

        float* nf_out = L ? out_nf : nf;
        k_aggr<<<(NN * 32 + 255) / 256, 256>>>(src, eidx, offs, elog, node_out, nf_out);
        ef_in = ef_out;
    }
}